// round 7
// baseline (speedup 1.0000x reference)
#include <cuda_runtime.h>
#include <math.h>
#include <stdint.h>

// ---------------- problem constants ----------------
#define BSZ      64
#define T_STEPS  150
#define IN_DIM   120
#define HID      1024
#define OUT_DIM  35
#define NB       8
#define NCOLS    8192          // HID*NB
#define ROWS     9600          // T_STEPS*BSZ
#define TB       16            // (t,b) rows per gemm group
#define GROUPS   600           // ROWS/TB
#define SPAD     20            // padded smem row stride (floats), 80B: float4-aligned, 8 bank slots
#define NNZ1     15            // IN_DIM/NB
#define NNZ2     128           // HID/NB

// ---------------- scratch (device globals; no allocation allowed) ----------------
__device__ float g_D [ (size_t)ROWS * NCOLS ];        // 314.6 MB dense branch-input buffer (reused per layer)
__device__ float g_sT[ (size_t)GROUPS * HID * TB ];   // spikes, transposed [g][i][16] (reused per layer)
__device__ float g_xT[ (size_t)GROUPS * IN_DIM * TB ];// input, transposed  [g][i][16]
__device__ float g_r [ (size_t)ROWS * OUT_DIM ];      // readout pre-scan
__device__ int   g_idx1[NNZ1 * NCOLS];
__device__ float g_val1[NNZ1 * NCOLS];
__device__ int   g_idx2[NNZ2 * NCOLS];
__device__ float g_val2[NNZ2 * NCOLS];
__device__ int   g_idx3[NNZ2 * NCOLS];
__device__ float g_val3[NNZ2 * NCOLS];
__device__ int   g_flag;                               // mask dtype: 0=u8, 1=i32, 2=f32

// ---------------- mask dtype detector ----------------
// Invariant: mask row 0 (layer 1) has exactly NNZ1=15 ones among IN_DIM=120 entries.
// Reading 480 bytes is safe under every candidate dtype.
__global__ void detect_mask(const void* m) {
    if (threadIdx.x != 0 || blockIdx.x != 0) return;
    const int*   mi = (const int*)m;
    const float* mf = (const float*)m;
    int  si = 0;   bool oki = true;
    for (int i = 0; i < IN_DIM; i++) { int v = mi[i]; if (v != 0 && v != 1) oki = false; si += v; }
    float sf = 0.f; bool okf = true;
    for (int i = 0; i < IN_DIM; i++) { float v = mf[i]; if (v != 0.f && v != 1.f) okf = false; sf += v; }
    int f = 0;
    if (oki && si == NNZ1) f = 1;
    else if (okf && sf == (float)NNZ1) f = 2;
    g_flag = f;
}

// ---------------- CSR build: per output row j, exactly `nnz` (idx,val) pairs ----------------
// Deterministic (sequential scan per row). Layout transposed: idxT[k*NCOLS + j].
__global__ void build_csr(const void* mask, const float* __restrict__ w,
                          int* __restrict__ idxT, float* __restrict__ valT,
                          int sdim, int nnz) {
    int j = blockIdx.x * blockDim.x + threadIdx.x;
    if (j >= NCOLS) return;
    const int f = g_flag;
    const unsigned char* mb = (const unsigned char*)mask;
    const int*           mi = (const int*)mask;
    const float*         mf = (const float*)mask;
    int k = 0;
    for (int i = 0; i < sdim; i++) {
        bool on;
        if (f == 1)      on = mi[(size_t)j * sdim + i] != 0;
        else if (f == 2) on = mf[(size_t)j * sdim + i] != 0.f;
        else             on = mb[(size_t)j * sdim + i] != 0;
        if (on && k < nnz) {
            idxT[k * NCOLS + j] = i;
            valT[k * NCOLS + j] = w[(size_t)j * sdim + i];
            k++;
        }
    }
    for (; k < nnz; k++) { idxT[k * NCOLS + j] = 0; valT[k * NCOLS + j] = 0.f; }
}

// ---------------- transpose x: [b][t][i] -> xT[(t*64+b)/16][i][ (t*64+b)%16 ] ----------------
__global__ void transpose_x(const float* __restrict__ x, float* __restrict__ xT) {
    int u = blockIdx.x * blockDim.x + threadIdx.x;
    if (u >= ROWS * IN_DIM) return;
    int row = u / IN_DIM;
    int i   = u - row * IN_DIM;
    int t   = row >> 6;
    int b   = row & 63;
    xT[(size_t)(row >> 4) * (IN_DIM * TB) + i * TB + (row & 15)] =
        x[(size_t)(b * T_STEPS + t) * IN_DIM + i];
}

// ---------------- sparse "GEMM": D[row][j] = bias[j] + sum_k val[k][j]*S[row][idx[k][j]] ----------------
// One block: 16 (t,b) rows (one group) x 1024 columns. Thread: 4 j x 16 row accumulators.
template<int SDIM, int NNZ>
__global__ __launch_bounds__(256, 2)
void gemm_sparse(const float* __restrict__ sT, const int* __restrict__ idxT,
                 const float* __restrict__ valT, const float* __restrict__ bias,
                 float* __restrict__ D) {
    extern __shared__ float s_sm[];            // [SDIM][SPAD]
    const int tid = threadIdx.x;
    const int g   = blockIdx.y;

    // stage this group's input slice, padded for bank spreading
    const float* src = sT + (size_t)g * (SDIM * TB);
    for (int u = tid; u < SDIM * TB; u += 256)
        s_sm[(u >> 4) * SPAD + (u & 15)] = src[u];
    __syncthreads();

    const int j0 = blockIdx.x * 1024 + tid;
    float acc[4][16];
#pragma unroll
    for (int c = 0; c < 4; c++) {
        float bv = bias[j0 + c * 256];
#pragma unroll
        for (int r = 0; r < 16; r++) acc[c][r] = bv;
    }

    // software-pipelined idx/val stream (L2-resident)
    int   cidx[4]; float cval[4];
#pragma unroll
    for (int c = 0; c < 4; c++) { cidx[c] = idxT[j0 + c * 256]; cval[c] = valT[j0 + c * 256]; }

#pragma unroll 4
    for (int k = 0; k < NNZ; k++) {
        int idx[4]; float val[4];
#pragma unroll
        for (int c = 0; c < 4; c++) { idx[c] = cidx[c]; val[c] = cval[c]; }
        if (k + 1 < NNZ) {
            const int off = (k + 1) * NCOLS + j0;
#pragma unroll
            for (int c = 0; c < 4; c++) { cidx[c] = idxT[off + c * 256]; cval[c] = valT[off + c * 256]; }
        }
#pragma unroll
        for (int c = 0; c < 4; c++) {
            const float4* sp = reinterpret_cast<const float4*>(s_sm + idx[c] * SPAD);
            float4 a0 = sp[0], a1 = sp[1], a2 = sp[2], a3 = sp[3];
            float  v  = val[c];
            acc[c][ 0] += v * a0.x; acc[c][ 1] += v * a0.y; acc[c][ 2] += v * a0.z; acc[c][ 3] += v * a0.w;
            acc[c][ 4] += v * a1.x; acc[c][ 5] += v * a1.y; acc[c][ 6] += v * a1.z; acc[c][ 7] += v * a1.w;
            acc[c][ 8] += v * a2.x; acc[c][ 9] += v * a2.y; acc[c][10] += v * a2.z; acc[c][11] += v * a2.w;
            acc[c][12] += v * a3.x; acc[c][13] += v * a3.y; acc[c][14] += v * a3.z; acc[c][15] += v * a3.w;
        }
    }

#pragma unroll
    for (int c = 0; c < 4; c++)
#pragma unroll
        for (int r = 0; r < 16; r++)
            D[(size_t)(g * TB + r) * NCOLS + j0 + c * 256] = acc[c][r];
}

// ---------------- fused branch-decay + membrane scan + spike ----------------
// Thread per (b,h). Reads D[row][h*8..h*8+8), writes spikes transposed for the next gemm.
__global__ __launch_bounds__(256)
void scan_layer(const float* __restrict__ D, const float* __restrict__ tau_m,
                const float* __restrict__ tau_n, float* __restrict__ sOut) {
    int tid = blockIdx.x * 256 + threadIdx.x;       // 0 .. 65535
    int b = tid >> 10, h = tid & 1023;

    float beta[8], omb[8];
#pragma unroll
    for (int n = 0; n < 8; n++) {
        float bb = 1.f / (1.f + expf(-tau_n[h * 8 + n]));
        beta[n] = bb; omb[n] = 1.f - bb;
    }
    float alpha = 1.f / (1.f + expf(-tau_m[h]));
    float oma   = 1.f - alpha;

    float d[8]; 
#pragma unroll
    for (int n = 0; n < 8; n++) d[n] = 0.f;
    float mem = 0.f, spk = 0.f;

    // prefetch t=0
    const float* base = D + (size_t)h * 8;
    float4 n0 = *(const float4*)(base + (size_t)b * NCOLS);
    float4 n1 = *(const float4*)(base + (size_t)b * NCOLS + 4);

    for (int t = 0; t < T_STEPS; t++) {
        float4 q0 = n0, q1 = n1;
        if (t + 1 < T_STEPS) {
            size_t roff = (size_t)((t + 1) * 64 + b) * NCOLS;
            n0 = *(const float4*)(base + roff);
            n1 = *(const float4*)(base + roff + 4);
        }
        d[0] = beta[0] * d[0] + omb[0] * q0.x;
        d[1] = beta[1] * d[1] + omb[1] * q0.y;
        d[2] = beta[2] * d[2] + omb[2] * q0.z;
        d[3] = beta[3] * d[3] + omb[3] * q0.w;
        d[4] = beta[4] * d[4] + omb[4] * q1.x;
        d[5] = beta[5] * d[5] + omb[5] * q1.y;
        d[6] = beta[6] * d[6] + omb[6] * q1.z;
        d[7] = beta[7] * d[7] + omb[7] * q1.w;
        float l = ((d[0] + d[1]) + (d[2] + d[3])) + ((d[4] + d[5]) + (d[6] + d[7]));
        mem = mem * alpha + oma * l - spk;           // VTH*spk, VTH=1
        spk = (mem > 1.0f) ? 1.0f : 0.0f;            // act_fun(mem - VTH)
        int row = t * 64 + b;
        sOut[(size_t)(row >> 4) * (HID * TB) + h * TB + (row & 15)] = spk;
    }
}

// ---------------- readout GEMM: r[row][o] = br[o] + s3[row]·wr[o] ----------------
__global__ __launch_bounds__(256)
void readout_k(const float* __restrict__ sT, const float* __restrict__ wr,
               const float* __restrict__ br, float* __restrict__ rOut) {
    int g = blockIdx.x;
    const float* sg = sT + (size_t)g * (HID * TB);
    for (int p = threadIdx.x; p < OUT_DIM * TB; p += 256) {
        int o  = p >> 4;
        int rr = p & 15;
        const float* wrow = wr + o * HID;
        float sum = br[o];
#pragma unroll 4
        for (int i = 0; i < HID; i++) sum += sg[i * TB + rr] * wrow[i];
        rOut[(size_t)(g * TB + rr) * OUT_DIM + o] = sum;
    }
}

// ---------------- readout leaky scan + mean + log_softmax ----------------
__global__ void final_k(const float* __restrict__ rIn, const float* __restrict__ tau_mr,
                        float* __restrict__ out) {
    int b = blockIdx.x;
    int o = threadIdx.x;                     // blockDim = 64, only o<35 active
    __shared__ float sv[64];
    __shared__ float s_mx, s_ls;
    float acc = 0.f;
    if (o < OUT_DIM) {
        float alpha = 1.f / (1.f + expf(-tau_mr[o]));
        float oma = 1.f - alpha;
        float mr = 0.f;
        for (int t = 0; t < T_STEPS; t++) {
            mr = mr * alpha + oma * rIn[(size_t)(t * 64 + b) * OUT_DIM + o];
            acc += mr;
        }
        acc /= (float)T_STEPS;
    }
    sv[o] = (o < OUT_DIM) ? acc : -1e30f;
    __syncthreads();
    if (o == 0) {
        float m = -1e30f;
        for (int i = 0; i < OUT_DIM; i++) m = fmaxf(m, sv[i]);
        float s = 0.f;
        for (int i = 0; i < OUT_DIM; i++) s += expf(sv[i] - m);
        s_mx = m; s_ls = logf(s);
    }
    __syncthreads();
    if (o < OUT_DIM) out[b * OUT_DIM + o] = sv[o] - s_mx - s_ls;
}

// ---------------- launch ----------------
extern "C" void kernel_launch(void* const* d_in, const int* in_sizes, int n_in,
                              void* d_out, int out_size) {
    (void)in_sizes; (void)n_in; (void)out_size;
    const float* x   = (const float*)d_in[0];
    const float* w1  = (const float*)d_in[1];
    const float* b1  = (const float*)d_in[2];
    const float* tm1 = (const float*)d_in[3];
    const float* tn1 = (const float*)d_in[4];
    const float* w2  = (const float*)d_in[5];
    const float* b2  = (const float*)d_in[6];
    const float* tm2 = (const float*)d_in[7];
    const float* tn2 = (const float*)d_in[8];
    const float* w3  = (const float*)d_in[9];
    const float* b3  = (const float*)d_in[10];
    const float* tm3 = (const float*)d_in[11];
    const float* tn3 = (const float*)d_in[12];
    const float* wr  = (const float*)d_in[13];
    const float* br  = (const float*)d_in[14];
    const float* tmr = (const float*)d_in[15];
    const void*  m1  = d_in[16];
    const void*  m2  = d_in[17];
    const void*  m3  = d_in[18];
    float* out = (float*)d_out;

    void *pD, *psT, *pxT, *pr, *pi1, *pv1, *pi2, *pv2, *pi3, *pv3;
    cudaGetSymbolAddress(&pD,  g_D);
    cudaGetSymbolAddress(&psT, g_sT);
    cudaGetSymbolAddress(&pxT, g_xT);
    cudaGetSymbolAddress(&pr,  g_r);
    cudaGetSymbolAddress(&pi1, g_idx1);  cudaGetSymbolAddress(&pv1, g_val1);
    cudaGetSymbolAddress(&pi2, g_idx2);  cudaGetSymbolAddress(&pv2, g_val2);
    cudaGetSymbolAddress(&pi3, g_idx3);  cudaGetSymbolAddress(&pv3, g_val3);

    // opt-in 80KB dynamic smem for the big gemm instantiation (idempotent, non-stream host call)
    cudaFuncSetAttribute(gemm_sparse<HID, NNZ2>,
                         cudaFuncAttributeMaxDynamicSharedMemorySize, HID * SPAD * 4);

    // 1) mask dtype + CSR build (per-launch; cheap)
    detect_mask<<<1, 32>>>(m1);
    build_csr<<<NCOLS / 256, 256>>>(m1, w1, (int*)pi1, (float*)pv1, IN_DIM, NNZ1);
    build_csr<<<NCOLS / 256, 256>>>(m2, w2, (int*)pi2, (float*)pv2, HID,    NNZ2);
    build_csr<<<NCOLS / 256, 256>>>(m3, w3, (int*)pi3, (float*)pv3, HID,    NNZ2);

    // 2) input transpose
    transpose_x<<<(ROWS * IN_DIM + 255) / 256, 256>>>(x, (float*)pxT);

    dim3 gg(NCOLS / 1024, GROUPS);

    // 3) layer 1
    gemm_sparse<IN_DIM, NNZ1><<<gg, 256, IN_DIM * SPAD * 4>>>(
        (const float*)pxT, (const int*)pi1, (const float*)pv1, b1, (float*)pD);
    scan_layer<<<(BSZ * HID) / 256, 256>>>((const float*)pD, tm1, tn1, (float*)psT);

    // 4) layer 2
    gemm_sparse<HID, NNZ2><<<gg, 256, HID * SPAD * 4>>>(
        (const float*)psT, (const int*)pi2, (const float*)pv2, b2, (float*)pD);
    scan_layer<<<(BSZ * HID) / 256, 256>>>((const float*)pD, tm2, tn2, (float*)psT);

    // 5) layer 3
    gemm_sparse<HID, NNZ2><<<gg, 256, HID * SPAD * 4>>>(
        (const float*)psT, (const int*)pi3, (const float*)pv3, b3, (float*)pD);
    scan_layer<<<(BSZ * HID) / 256, 256>>>((const float*)pD, tm3, tn3, (float*)psT);

    // 6) readout + final scan + log_softmax
    readout_k<<<GROUPS, 256>>>((const float*)psT, wr, br, (float*)pr);
    final_k<<<BSZ, 64>>>((const float*)pr, tmr, out);
}

// round 8
// speedup vs baseline: 3.2749x; 3.2749x over previous
#include <cuda_runtime.h>
#include <math.h>
#include <stdint.h>

// ---------------- problem constants ----------------
#define BSZ      64
#define T_STEPS  150
#define IN_DIM   120
#define HID      1024
#define OUT_DIM  35
#define NB       8
#define NCOLS    8192          // HID*NB
#define ROWS     9600          // T_STEPS*BSZ
#define TB       16            // (t,b) rows per gemm group
#define GROUPS   600           // ROWS/TB
#define SPAD     20            // padded smem row stride (floats)
#define NNZ1     15            // IN_DIM/NB
#define NNZ2     128           // HID/NB

// ---------------- scratch (device globals; no allocation allowed) ----------------
__device__ float    g_D   [(size_t)ROWS * NCOLS];       // dense branch-input buffer (reused per layer)
__device__ unsigned g_bits[(size_t)GROUPS * HID];       // spike bitmasks: [group][i], 16 valid bits
__device__ float    g_sT  [(size_t)GROUPS * HID * TB];  // layer-3 spikes (float) for readout
__device__ float    g_xT  [(size_t)GROUPS * IN_DIM * TB];
__device__ float    g_r   [(size_t)ROWS * OUT_DIM];
__device__ uint2    g_pv1 [NNZ1 * NCOLS];               // packed (idx, val-bits), layout [k][j]
__device__ uint2    g_pv2 [NNZ2 * NCOLS];
__device__ uint2    g_pv3 [NNZ2 * NCOLS];
__device__ int      g_flag;                             // mask dtype: 0=u8, 1=i32, 2=f32

// ---------------- mask dtype detector ----------------
// Invariant: mask row 0 (layer 1) has exactly NNZ1=15 ones among IN_DIM=120 entries.
__global__ void detect_mask(const void* m) {
    if (threadIdx.x != 0 || blockIdx.x != 0) return;
    const int*   mi = (const int*)m;
    const float* mf = (const float*)m;
    int  si = 0;   bool oki = true;
    for (int i = 0; i < IN_DIM; i++) { int v = mi[i]; if (v != 0 && v != 1) oki = false; si += v; }
    float sf = 0.f; bool okf = true;
    for (int i = 0; i < IN_DIM; i++) { float v = mf[i]; if (v != 0.f && v != 1.f) okf = false; sf += v; }
    int f = 0;
    if (oki && si == NNZ1) f = 1;
    else if (okf && sf == (float)NNZ1) f = 2;
    g_flag = f;
}

// ---------------- CSR build: warp per output row j, ballot compaction ----------------
// Deterministic: ballot preserves ascending index order.
__global__ void build_csr_warp(const void* mask, const float* __restrict__ w,
                               uint2* __restrict__ pv, int sdim, int nnz) {
    int gtid = blockIdx.x * blockDim.x + threadIdx.x;
    int j    = gtid >> 5;
    int lane = gtid & 31;
    if (j >= NCOLS) return;
    const int f = g_flag;
    int base = 0;
    int iters = (sdim + 31) >> 5;
    for (int it = 0; it < iters; it++) {
        int i = it * 32 + lane;
        bool on = false;
        if (i < sdim) {
            if (f == 1)      on = ((const int*)mask)[(size_t)j * sdim + i] != 0;
            else if (f == 2) on = ((const float*)mask)[(size_t)j * sdim + i] != 0.f;
            else             on = ((const unsigned char*)mask)[(size_t)j * sdim + i] != 0;
        }
        unsigned bal = __ballot_sync(0xFFFFFFFFu, on);
        if (on) {
            int k = base + __popc(bal & ((1u << lane) - 1u));
            if (k < nnz)
                pv[k * NCOLS + j] = make_uint2((unsigned)i,
                                               __float_as_uint(w[(size_t)j * sdim + i]));
        }
        base += __popc(bal);
    }
    if (lane == 0)
        for (int k = base; k < nnz; k++) pv[k * NCOLS + j] = make_uint2(0u, 0u);
}

// ---------------- transpose x: [b][t][i] -> xT[group][i][row%16] ----------------
__global__ void transpose_x(const float* __restrict__ x, float* __restrict__ xT) {
    int u = blockIdx.x * blockDim.x + threadIdx.x;
    if (u >= ROWS * IN_DIM) return;
    int row = u / IN_DIM;
    int i   = u - row * IN_DIM;
    int t   = row >> 6;
    int b   = row & 63;
    xT[(size_t)(row >> 4) * (IN_DIM * TB) + i * TB + (row & 15)] =
        x[(size_t)(b * T_STEPS + t) * IN_DIM + i];
}

// ---------------- layer-1 gemm (float input path, NNZ1=15) ----------------
__global__ __launch_bounds__(256, 2)
void gemm_float(const float* __restrict__ sT, const uint2* __restrict__ pv,
                const float* __restrict__ bias, float* __restrict__ D) {
    __shared__ float s_sm[IN_DIM * SPAD];
    const int tid = threadIdx.x;
    const int g   = blockIdx.y;

    const float* src = sT + (size_t)g * (IN_DIM * TB);
    for (int u = tid; u < IN_DIM * TB; u += 256)
        s_sm[(u >> 4) * SPAD + (u & 15)] = src[u];
    __syncthreads();

    const int j0 = blockIdx.x * 1024 + tid;
    float acc[4][16];
#pragma unroll
    for (int c = 0; c < 4; c++) {
        float bv = bias[j0 + c * 256];
#pragma unroll
        for (int r = 0; r < 16; r++) acc[c][r] = bv;
    }

    uint2 cpv[4];
#pragma unroll
    for (int c = 0; c < 4; c++) cpv[c] = pv[j0 + c * 256];

#pragma unroll 3
    for (int k = 0; k < NNZ1; k++) {
        uint2 cur[4];
#pragma unroll
        for (int c = 0; c < 4; c++) cur[c] = cpv[c];
        if (k + 1 < NNZ1) {
            const int off = (k + 1) * NCOLS + j0;
#pragma unroll
            for (int c = 0; c < 4; c++) cpv[c] = pv[off + c * 256];
        }
#pragma unroll
        for (int c = 0; c < 4; c++) {
            const float4* sp = reinterpret_cast<const float4*>(s_sm + cur[c].x * SPAD);
            float4 a0 = sp[0], a1 = sp[1], a2 = sp[2], a3 = sp[3];
            float  v  = __uint_as_float(cur[c].y);
            acc[c][ 0] += v * a0.x; acc[c][ 1] += v * a0.y; acc[c][ 2] += v * a0.z; acc[c][ 3] += v * a0.w;
            acc[c][ 4] += v * a1.x; acc[c][ 5] += v * a1.y; acc[c][ 6] += v * a1.z; acc[c][ 7] += v * a1.w;
            acc[c][ 8] += v * a2.x; acc[c][ 9] += v * a2.y; acc[c][10] += v * a2.z; acc[c][11] += v * a2.w;
            acc[c][12] += v * a3.x; acc[c][13] += v * a3.y; acc[c][14] += v * a3.z; acc[c][15] += v * a3.w;
        }
    }

#pragma unroll
    for (int c = 0; c < 4; c++)
#pragma unroll
        for (int r = 0; r < 16; r++)
            D[(size_t)(g * TB + r) * NCOLS + j0 + c * 256] = acc[c][r];
}

// ---------------- layer-2/3 gemm (binary spike input, bitmask path) ----------------
// Inner loop: one LDS.32 bitmask per (k,c) + 16 predicated FADDs. Exact.
__global__ __launch_bounds__(256, 2)
void gemm_bits(const unsigned* __restrict__ bitsIn, const uint2* __restrict__ pv,
               const float* __restrict__ bias, float* __restrict__ D) {
    __shared__ unsigned s_bits[HID];
    const int tid = threadIdx.x;
    const int g   = blockIdx.y;

    const unsigned* src = bitsIn + (size_t)g * HID;
    for (int u = tid; u < HID; u += 256) s_bits[u] = src[u];
    __syncthreads();

    const int j0 = blockIdx.x * 1024 + tid;
    float acc[4][16];
#pragma unroll
    for (int c = 0; c < 4; c++) {
        float bv = bias[j0 + c * 256];
#pragma unroll
        for (int r = 0; r < 16; r++) acc[c][r] = bv;
    }

    uint2 cpv[4];
#pragma unroll
    for (int c = 0; c < 4; c++) cpv[c] = pv[j0 + c * 256];

#pragma unroll 2
    for (int k = 0; k < NNZ2; k++) {
        unsigned mm[4]; float vv[4];
#pragma unroll
        for (int c = 0; c < 4; c++) {
            mm[c] = s_bits[cpv[c].x];
            vv[c] = __uint_as_float(cpv[c].y);
        }
        if (k + 1 < NNZ2) {
            const int off = (k + 1) * NCOLS + j0;
#pragma unroll
            for (int c = 0; c < 4; c++) cpv[c] = pv[off + c * 256];
        }
#pragma unroll
        for (int c = 0; c < 4; c++) {
            const unsigned m = mm[c];
            const float    v = vv[c];
#pragma unroll
            for (int r = 0; r < 16; r++)
                if (m & (1u << r)) acc[c][r] += v;
        }
    }

#pragma unroll
    for (int c = 0; c < 4; c++)
#pragma unroll
        for (int r = 0; r < 16; r++)
            D[(size_t)(g * TB + r) * NCOLS + j0 + c * 256] = acc[c][r];
}

// ---------------- scan producing spike BITMASKS (layers 1,2) ----------------
// Warp = fixed h, 32 consecutive b -> ballot gives two 16-row group words per t.
__global__ __launch_bounds__(256)
void scan_bits(const float* __restrict__ D, const float* __restrict__ tau_m,
               const float* __restrict__ tau_n, unsigned* __restrict__ bitsOut) {
    int tid  = blockIdx.x * 256 + threadIdx.x;      // 0 .. 65535
    int h    = tid >> 6;
    int b    = tid & 63;
    int lane = threadIdx.x & 31;

    float beta[8], omb[8];
#pragma unroll
    for (int n = 0; n < 8; n++) {
        float bb = 1.f / (1.f + expf(-tau_n[h * 8 + n]));
        beta[n] = bb; omb[n] = 1.f - bb;
    }
    float alpha = 1.f / (1.f + expf(-tau_m[h]));
    float oma   = 1.f - alpha;

    float d[8];
#pragma unroll
    for (int n = 0; n < 8; n++) d[n] = 0.f;
    float mem = 0.f, spk = 0.f;

    const float* base = D + (size_t)h * 8;
    float4 n0 = *(const float4*)(base + (size_t)b * NCOLS);
    float4 n1 = *(const float4*)(base + (size_t)b * NCOLS + 4);

    for (int t = 0; t < T_STEPS; t++) {
        float4 q0 = n0, q1 = n1;
        if (t + 1 < T_STEPS) {
            size_t roff = (size_t)((t + 1) * 64 + b) * NCOLS;
            n0 = *(const float4*)(base + roff);
            n1 = *(const float4*)(base + roff + 4);
        }
        d[0] = beta[0] * d[0] + omb[0] * q0.x;
        d[1] = beta[1] * d[1] + omb[1] * q0.y;
        d[2] = beta[2] * d[2] + omb[2] * q0.z;
        d[3] = beta[3] * d[3] + omb[3] * q0.w;
        d[4] = beta[4] * d[4] + omb[4] * q1.x;
        d[5] = beta[5] * d[5] + omb[5] * q1.y;
        d[6] = beta[6] * d[6] + omb[6] * q1.z;
        d[7] = beta[7] * d[7] + omb[7] * q1.w;
        float l = ((d[0] + d[1]) + (d[2] + d[3])) + ((d[4] + d[5]) + (d[6] + d[7]));
        mem = mem * alpha + oma * l - spk;
        bool fired = mem > 1.0f;
        spk = fired ? 1.0f : 0.0f;
        unsigned bal = __ballot_sync(0xFFFFFFFFu, fired);
        if (lane == 0) {
            int gbase = (t * 64 + (b & ~31)) >> 4;         // first 16-row group of this warp
            bitsOut[(size_t)gbase       * HID + h] = bal & 0xFFFFu;
            bitsOut[(size_t)(gbase + 1) * HID + h] = bal >> 16;
        }
    }
}

// ---------------- scan producing FLOAT spikes (layer 3, feeds readout) ----------------
__global__ __launch_bounds__(256)
void scan_float(const float* __restrict__ D, const float* __restrict__ tau_m,
                const float* __restrict__ tau_n, float* __restrict__ sOut) {
    int tid = blockIdx.x * 256 + threadIdx.x;
    int b = tid >> 10, h = tid & 1023;

    float beta[8], omb[8];
#pragma unroll
    for (int n = 0; n < 8; n++) {
        float bb = 1.f / (1.f + expf(-tau_n[h * 8 + n]));
        beta[n] = bb; omb[n] = 1.f - bb;
    }
    float alpha = 1.f / (1.f + expf(-tau_m[h]));
    float oma   = 1.f - alpha;

    float d[8];
#pragma unroll
    for (int n = 0; n < 8; n++) d[n] = 0.f;
    float mem = 0.f, spk = 0.f;

    const float* base = D + (size_t)h * 8;
    float4 n0 = *(const float4*)(base + (size_t)b * NCOLS);
    float4 n1 = *(const float4*)(base + (size_t)b * NCOLS + 4);

    for (int t = 0; t < T_STEPS; t++) {
        float4 q0 = n0, q1 = n1;
        if (t + 1 < T_STEPS) {
            size_t roff = (size_t)((t + 1) * 64 + b) * NCOLS;
            n0 = *(const float4*)(base + roff);
            n1 = *(const float4*)(base + roff + 4);
        }
        d[0] = beta[0] * d[0] + omb[0] * q0.x;
        d[1] = beta[1] * d[1] + omb[1] * q0.y;
        d[2] = beta[2] * d[2] + omb[2] * q0.z;
        d[3] = beta[3] * d[3] + omb[3] * q0.w;
        d[4] = beta[4] * d[4] + omb[4] * q1.x;
        d[5] = beta[5] * d[5] + omb[5] * q1.y;
        d[6] = beta[6] * d[6] + omb[6] * q1.z;
        d[7] = beta[7] * d[7] + omb[7] * q1.w;
        float l = ((d[0] + d[1]) + (d[2] + d[3])) + ((d[4] + d[5]) + (d[6] + d[7]));
        mem = mem * alpha + oma * l - spk;
        spk = (mem > 1.0f) ? 1.0f : 0.0f;
        int row = t * 64 + b;
        sOut[(size_t)(row >> 4) * (HID * TB) + h * TB + (row & 15)] = spk;
    }
}

// ---------------- readout GEMM: r[row][o] = br[o] + s3[row]·wr[o] ----------------
__global__ __launch_bounds__(256)
void readout_k(const float* __restrict__ sT, const float* __restrict__ wr,
               const float* __restrict__ br, float* __restrict__ rOut) {
    int g = blockIdx.x;
    const float* sg = sT + (size_t)g * (HID * TB);
    for (int p = threadIdx.x; p < OUT_DIM * TB; p += 256) {
        int o  = p >> 4;
        int rr = p & 15;
        const float* wrow = wr + o * HID;
        float s0 = 0.f, s1 = 0.f, s2 = 0.f, s3 = 0.f;
#pragma unroll 2
        for (int i = 0; i < HID; i += 4) {
            s0 += sg[(i + 0) * TB + rr] * wrow[i + 0];
            s1 += sg[(i + 1) * TB + rr] * wrow[i + 1];
            s2 += sg[(i + 2) * TB + rr] * wrow[i + 2];
            s3 += sg[(i + 3) * TB + rr] * wrow[i + 3];
        }
        rOut[(size_t)(g * TB + rr) * OUT_DIM + o] = br[o] + ((s0 + s1) + (s2 + s3));
    }
}

// ---------------- readout leaky scan + mean + log_softmax ----------------
__global__ void final_k(const float* __restrict__ rIn, const float* __restrict__ tau_mr,
                        float* __restrict__ out) {
    int b = blockIdx.x;
    int o = threadIdx.x;                     // blockDim = 64, only o<35 active
    __shared__ float sv[64];
    __shared__ float s_mx, s_ls;
    float acc = 0.f;
    if (o < OUT_DIM) {
        float alpha = 1.f / (1.f + expf(-tau_mr[o]));
        float oma = 1.f - alpha;
        float mr = 0.f;
        for (int t = 0; t < T_STEPS; t++) {
            mr = mr * alpha + oma * rIn[(size_t)(t * 64 + b) * OUT_DIM + o];
            acc += mr;
        }
        acc /= (float)T_STEPS;
    }
    sv[o] = (o < OUT_DIM) ? acc : -1e30f;
    __syncthreads();
    if (o == 0) {
        float m = -1e30f;
        for (int i = 0; i < OUT_DIM; i++) m = fmaxf(m, sv[i]);
        float s = 0.f;
        for (int i = 0; i < OUT_DIM; i++) s += expf(sv[i] - m);
        s_mx = m; s_ls = logf(s);
    }
    __syncthreads();
    if (o < OUT_DIM) out[b * OUT_DIM + o] = sv[o] - s_mx - s_ls;
}

// ---------------- launch ----------------
extern "C" void kernel_launch(void* const* d_in, const int* in_sizes, int n_in,
                              void* d_out, int out_size) {
    (void)in_sizes; (void)n_in; (void)out_size;
    const float* x   = (const float*)d_in[0];
    const float* w1  = (const float*)d_in[1];
    const float* b1  = (const float*)d_in[2];
    const float* tm1 = (const float*)d_in[3];
    const float* tn1 = (const float*)d_in[4];
    const float* w2  = (const float*)d_in[5];
    const float* b2  = (const float*)d_in[6];
    const float* tm2 = (const float*)d_in[7];
    const float* tn2 = (const float*)d_in[8];
    const float* w3  = (const float*)d_in[9];
    const float* b3  = (const float*)d_in[10];
    const float* tm3 = (const float*)d_in[11];
    const float* tn3 = (const float*)d_in[12];
    const float* wr  = (const float*)d_in[13];
    const float* br  = (const float*)d_in[14];
    const float* tmr = (const float*)d_in[15];
    const void*  m1  = d_in[16];
    const void*  m2  = d_in[17];
    const void*  m3  = d_in[18];
    float* out = (float*)d_out;

    void *pD, *pB, *psT, *pxT, *pr, *pv1, *pv2, *pv3;
    cudaGetSymbolAddress(&pD,  g_D);
    cudaGetSymbolAddress(&pB,  g_bits);
    cudaGetSymbolAddress(&psT, g_sT);
    cudaGetSymbolAddress(&pxT, g_xT);
    cudaGetSymbolAddress(&pr,  g_r);
    cudaGetSymbolAddress(&pv1, g_pv1);
    cudaGetSymbolAddress(&pv2, g_pv2);
    cudaGetSymbolAddress(&pv3, g_pv3);

    // 1) mask dtype + CSR builds (warp-ballot compaction)
    detect_mask<<<1, 32>>>(m1);
    build_csr_warp<<<NCOLS * 32 / 256, 256>>>(m1, w1, (uint2*)pv1, IN_DIM, NNZ1);
    build_csr_warp<<<NCOLS * 32 / 256, 256>>>(m2, w2, (uint2*)pv2, HID,    NNZ2);
    build_csr_warp<<<NCOLS * 32 / 256, 256>>>(m3, w3, (uint2*)pv3, HID,    NNZ2);

    // 2) input transpose
    transpose_x<<<(ROWS * IN_DIM + 255) / 256, 256>>>(x, (float*)pxT);

    dim3 gg(NCOLS / 1024, GROUPS);

    // 3) layer 1 (float input) -> spike bitmasks
    gemm_float<<<gg, 256>>>((const float*)pxT, (const uint2*)pv1, b1, (float*)pD);
    scan_bits<<<(BSZ * HID) / 256, 256>>>((const float*)pD, tm1, tn1, (unsigned*)pB);

    // 4) layer 2 (bitmask input) -> spike bitmasks
    gemm_bits<<<gg, 256>>>((const unsigned*)pB, (const uint2*)pv2, b2, (float*)pD);
    scan_bits<<<(BSZ * HID) / 256, 256>>>((const float*)pD, tm2, tn2, (unsigned*)pB);

    // 5) layer 3 (bitmask input) -> float spikes for readout
    gemm_bits<<<gg, 256>>>((const unsigned*)pB, (const uint2*)pv3, b3, (float*)pD);
    scan_float<<<(BSZ * HID) / 256, 256>>>((const float*)pD, tm3, tn3, (float*)psT);

    // 6) readout + final scan + log_softmax
    readout_k<<<GROUPS, 256>>>((const float*)psT, wr, br, (float*)pr);
    final_k<<<BSZ, 64>>>((const float*)pr, tmr, out);
}